// round 10
// baseline (speedup 1.0000x reference)
#include <cuda_runtime.h>
#include <cuda_fp16.h>
#include <math.h>

#define NN 10000
#define EE 160000

// ---------------- scratch (device globals; no allocations allowed) ----------
__device__ float g_Q[NN * 64];
__device__ float g_K[NN * 64];
__device__ float g_V[NN * 64];
__device__ uint4 g_MA4[NN * 64];   // NN x 512 halfs
__device__ uint4 g_MB4[NN * 64];
__device__ float g_deginv[NN];
__device__ int   g_cnt[NN];
__device__ int   g_ptr[NN + 1];
__device__ int   g_wp[NN];
__device__ int   g_eidx[EE];   // bucketed (unsorted) edge ids from k_place
__device__ int   g_src[EE];    // sorted-position source node (written by hop0)
__device__ float g_wt[EE];     // sorted-position norm weight (written by hop0)

// ---------------- setup ------------------------------------------------------
__global__ void k_count(const int* __restrict__ col) {
    int e = blockIdx.x * blockDim.x + threadIdx.x;
    if (e < EE) atomicAdd(&g_cnt[col[e]], 1);
}

// single-block exclusive scan of g_cnt -> g_ptr / g_wp ; also deginv
__global__ void k_scan() {
    __shared__ int s[1024];
    int t = threadIdx.x;
    const int CH = (NN + 1023) / 1024;
    int start = t * CH;
    int sum = 0;
    for (int i = 0; i < CH; i++) {
        int idx = start + i;
        if (idx < NN) sum += g_cnt[idx];
    }
    s[t] = sum;
    __syncthreads();
    for (int off = 1; off < 1024; off <<= 1) {
        int v = (t >= off) ? s[t - off] : 0;
        __syncthreads();
        s[t] += v;
        __syncthreads();
    }
    int run = (t == 0) ? 0 : s[t - 1];
    for (int i = 0; i < CH; i++) {
        int idx = start + i;
        if (idx < NN) {
            int c = g_cnt[idx];
            g_ptr[idx] = run;
            g_wp[idx]  = run;
            g_deginv[idx] = (c > 0) ? rsqrtf((float)c) : 0.0f;
            run += c;
        }
    }
    if (t == 0) g_ptr[NN] = s[1023];
}

__global__ void k_place(const int* __restrict__ col) {
    int e = blockIdx.x * blockDim.x + threadIdx.x;
    if (e < EE) {
        int c = col[e];
        int p = atomicAdd(&g_wp[c], 1);
        g_eidx[p] = e;
    }
}

// ---------------- Q/K/V GEMM + hidden init ----------------------------------
// 40 nodes/block (10000 = 250*40, NO guards), 256 threads.
// Thread owns col c (=tid&63) x 10 nodes (g+4p, p<10): 30 accumulators.
// Per k-step: 3 weight LDG + 10 smem loads + 30 FMAs -> FMA-pipe bound.
__global__ void __launch_bounds__(256) k_qkv(const float* __restrict__ x,
                      const float* __restrict__ Wq, const float* __restrict__ bq,
                      const float* __restrict__ Wk, const float* __restrict__ bk,
                      const float* __restrict__ Wv, const float* __restrict__ bv,
                      const float* __restrict__ hopwise, float* __restrict__ out) {
    __shared__ float sx[40 * 64];
    int n0 = blockIdx.x * 40;
    for (int idx = threadIdx.x; idx < 40 * 64; idx += 256)
        sx[idx] = x[n0 * 64 + idx];
    __syncthreads();

    int c = threadIdx.x & 63;
    int g = threadIdx.x >> 6;  // 0..3
    float aq[10], ak[10], av[10];
#pragma unroll
    for (int p = 0; p < 10; p++) { aq[p] = 0.f; ak[p] = 0.f; av[p] = 0.f; }

#pragma unroll 2
    for (int k = 0; k < 64; k++) {
        float wq = __ldg(Wq + k * 64 + c);
        float wk = __ldg(Wk + k * 64 + c);
        float wv = __ldg(Wv + k * 64 + c);
#pragma unroll
        for (int p = 0; p < 10; p++) {
            float xv = sx[(g + 4 * p) * 64 + k];
            aq[p] += xv * wq;
            ak[p] += xv * wk;
            av[p] += xv * wv;
        }
    }
    float hw0 = __ldg(hopwise);
    float bqc = __ldg(bq + c), bkc = __ldg(bk + c), bvc = __ldg(bv + c);
#pragma unroll
    for (int p = 0; p < 10; p++) {
        int n = n0 + g + 4 * p;
        g_Q[n * 64 + c] = fmaxf(aq[p] + bqc, 0.0f);
        g_K[n * 64 + c] = ak[p] + bkc;
        float v = av[p] + bvc;
        g_V[n * 64 + c] = v;
        out[n * 64 + c] = hw0 * v;
    }
}

// ---------------- fused epilogue (64 threads/node) ---------------------------
__device__ __forceinline__ void h_epilogue64(int n, int t, const float* acc,
                                             float hw, float* __restrict__ out) {
    float q = g_Q[n * 64 + t];
    float Hp[8];
#pragma unroll
    for (int j = 0; j < 8; j++) Hp[j] = q * acc[j];
#pragma unroll
    for (int off = 1; off < 8; off <<= 1) {
#pragma unroll
        for (int j = 0; j < 8; j++)
            Hp[j] += __shfl_xor_sync(0xffffffffu, Hp[j], off);
    }
    if ((t & 7) == 0) {
        float ss = 0.f;
#pragma unroll
        for (int j = 0; j < 8; j++) ss += Hp[j] * Hp[j];
        float nrm = sqrtf(ss * 0.125f);
        float sc = (nrm > 1.0f) ? (1.0f / nrm) : 1.0f;
        float c = hw * sc;
        int h = t >> 3;
        float4* op = (float4*)(out + n * 64 + h * 8);
        float4 o0 = op[0], o1 = op[1];
        o0.x += c * Hp[0]; o0.y += c * Hp[1]; o0.z += c * Hp[2]; o0.w += c * Hp[3];
        o1.x += c * Hp[4]; o1.y += c * Hp[5]; o1.z += c * Hp[6]; o1.w += c * Hp[7];
        op[0] = o0; op[1] = o1;
    }
}

__device__ __forceinline__ void acc8(float* a, uint4 A, float w) {
    const __half2* h = (const __half2*)&A;
#pragma unroll
    for (int q = 0; q < 4; q++) {
        float2 f = __half22float2(h[q]);
        a[2 * q]     += w * f.x;
        a[2 * q + 1] += w * f.y;
    }
}

__device__ __forceinline__ uint4 pack8(const float* a) {
    uint4 o;
    __half2* ho = (__half2*)&o;
#pragma unroll
    for (int q = 0; q < 4; q++)
        ho[q] = __float22half2_rn(make_float2(a[2 * q], a[2 * q + 1]));
    return o;
}

// ---------------- hop 0: sort buckets + outer product + fused H-update -------
__global__ void __launch_bounds__(256) k_hop0(const int* __restrict__ row,
                                              const float* __restrict__ ew,
                                              const float* __restrict__ ef,
                                              const float* __restrict__ hopwise,
                                              float* __restrict__ out) {
    __shared__ int   s_e[4][128];
    __shared__ int   s_r[4][128];
    __shared__ float s_w[4][128];
    __shared__ int   s_glob[4];

    int warp = threadIdx.x >> 5;
    int lane = threadIdx.x & 31;
    int ln   = warp >> 1;                 // local node 0..3
    int node = blockIdx.x * 4 + ln;       // NN divisible by 4
    int b = g_ptr[node], e2 = g_ptr[node + 1];
    int d = e2 - b;

    if ((warp & 1) == 0) {                // even warp: sort + metadata
        if (lane == 0) s_glob[ln] = 0;
        float dc = g_deginv[node];
        if (d > 0 && d <= 32) {
            int v = (lane < d) ? g_eidx[b + lane] : 0x7fffffff;
#pragma unroll
            for (int k = 2; k <= 32; k <<= 1) {
#pragma unroll
                for (int j = k >> 1; j > 0; j >>= 1) {
                    int other = __shfl_xor_sync(0xffffffffu, v, j);
                    bool higher = (lane & j) != 0;
                    bool asc = (lane & k) == 0;
                    v = (higher == asc) ? max(v, other) : min(v, other);
                }
            }
            if (lane < d) {
                int r = __ldg(row + v);
                float w = g_deginv[r] * dc * __ldg(ew + v);
                s_e[ln][lane] = v;
                s_r[ln][lane] = r;
                s_w[ln][lane] = w;
                g_src[b + lane] = r;
                g_wt[b + lane]  = w;
            }
        } else if (d > 32 && d <= 128) {
            for (int i = lane; i < d; i += 32) s_e[ln][i] = g_eidx[b + i];
            __syncwarp();
            for (int ph = 0; ph < d; ph++) {
                int startp = ph & 1;
                for (int i = startp + 2 * lane; i + 1 < d; i += 64) {
                    int a = s_e[ln][i], c = s_e[ln][i + 1];
                    if (a > c) { s_e[ln][i] = c; s_e[ln][i + 1] = a; }
                }
                __syncwarp();
            }
            for (int i = lane; i < d; i += 32) {
                int e = s_e[ln][i];
                int r = __ldg(row + e);
                float w = g_deginv[r] * dc * __ldg(ew + e);
                s_r[ln][i] = r;
                s_w[ln][i] = w;
                g_src[b + i] = r;
                g_wt[b + i]  = w;
            }
        } else if (d > 128) {
            if (lane == 0) {
                s_glob[ln] = 1;
                for (int i = b + 1; i < e2; i++) {
                    int v = g_eidx[i];
                    int j = i - 1;
                    while (j >= b && g_eidx[j] > v) {
                        g_eidx[j + 1] = g_eidx[j];
                        j--;
                    }
                    g_eidx[j + 1] = v;
                }
            }
            __syncwarp();
            for (int i = b + lane; i < e2; i += 32) {
                int e = g_eidx[i];
                int r = __ldg(row + e);
                g_src[i] = r;
                g_wt[i]  = g_deginv[r] * dc * __ldg(ew + e);
            }
        }
    }
    __syncthreads();

    int t = threadIdx.x & 63;
    int h8 = (t >> 3) << 3;
    float acc[8];
#pragma unroll
    for (int j = 0; j < 8; j++) acc[j] = 0.0f;

    if (!s_glob[ln]) {
        int p = 0;
        for (; p + 4 <= d; p += 4) {
            float kv[4], fv[4], w[4];
            float4 va[4], vb[4];
#pragma unroll
            for (int q = 0; q < 4; q++) {
                int e = s_e[ln][p + q];
                int r = s_r[ln][p + q];
                w[q]  = s_w[ln][p + q];
                kv[q] = g_K[r * 64 + t];
                fv[q] = ef[(size_t)e * 64 + t];
                va[q] = *(const float4*)(g_V + r * 64 + h8);
                vb[q] = *(const float4*)(g_V + r * 64 + h8 + 4);
            }
#pragma unroll
            for (int q = 0; q < 4; q++) {
                float a = fmaxf(kv[q] + fv[q], 0.0f) * w[q];
                acc[0] += a * va[q].x; acc[1] += a * va[q].y;
                acc[2] += a * va[q].z; acc[3] += a * va[q].w;
                acc[4] += a * vb[q].x; acc[5] += a * vb[q].y;
                acc[6] += a * vb[q].z; acc[7] += a * vb[q].w;
            }
        }
        for (; p < d; p++) {
            int e = s_e[ln][p];
            int r = s_r[ln][p];
            float w0 = s_w[ln][p];
            float kv = g_K[r * 64 + t];
            float fv = ef[(size_t)e * 64 + t];
            float4 va = *(const float4*)(g_V + r * 64 + h8);
            float4 vb = *(const float4*)(g_V + r * 64 + h8 + 4);
            float a = fmaxf(kv + fv, 0.0f) * w0;
            acc[0] += a * va.x; acc[1] += a * va.y; acc[2] += a * va.z; acc[3] += a * va.w;
            acc[4] += a * vb.x; acc[5] += a * vb.y; acc[6] += a * vb.z; acc[7] += a * vb.w;
        }
    } else {
        for (int p = b; p < e2; p++) {
            int e = g_eidx[p];
            int r = g_src[p];
            float w0 = g_wt[p];
            float kv = g_K[r * 64 + t];
            float fv = ef[(size_t)e * 64 + t];
            float4 va = *(const float4*)(g_V + r * 64 + h8);
            float4 vb = *(const float4*)(g_V + r * 64 + h8 + 4);
            float a = fmaxf(kv + fv, 0.0f) * w0;
            acc[0] += a * va.x; acc[1] += a * va.y; acc[2] += a * va.z; acc[3] += a * va.w;
            acc[4] += a * vb.x; acc[5] += a * vb.y; acc[6] += a * vb.z; acc[7] += a * vb.w;
        }
    }

    g_MA4[(size_t)node * 64 + t] = pack8(acc);
    h_epilogue64(node, t, acc, __ldg(hopwise + 1), out);
}

// ---------------- prop hops + fused H-update (64 threads/node) ---------------
__global__ void __launch_bounds__(256) k_prop(const uint4* __restrict__ Msrc,
                                              uint4* __restrict__ Mdst, int writeM,
                                              int hop, const float* __restrict__ hopwise,
                                              float* __restrict__ out) {
    int node = blockIdx.x * 4 + (threadIdx.x >> 6);
    if (node >= NN) return;
    int t = threadIdx.x & 63;

    float acc[8];
#pragma unroll
    for (int j = 0; j < 8; j++) acc[j] = 0.0f;

    int beg = g_ptr[node], end = g_ptr[node + 1];
    int p = beg;
    for (; p + 8 <= end; p += 8) {
        uint4 A[8];
        float w[8];
#pragma unroll
        for (int q = 0; q < 8; q++) {
            int r = g_src[p + q];
            w[q] = g_wt[p + q];
            A[q] = Msrc[(size_t)r * 64 + t];
        }
#pragma unroll
        for (int q = 0; q < 8; q++) acc8(acc, A[q], w[q]);
    }
    for (; p + 4 <= end; p += 4) {
        uint4 A[4];
        float w[4];
#pragma unroll
        for (int q = 0; q < 4; q++) {
            int r = g_src[p + q];
            w[q] = g_wt[p + q];
            A[q] = Msrc[(size_t)r * 64 + t];
        }
#pragma unroll
        for (int q = 0; q < 4; q++) acc8(acc, A[q], w[q]);
    }
    for (; p < end; p++) {
        int r = g_src[p];
        float w0 = g_wt[p];
        uint4 A = Msrc[(size_t)r * 64 + t];
        acc8(acc, A, w0);
    }

    if (writeM) Mdst[(size_t)node * 64 + t] = pack8(acc);
    h_epilogue64(node, t, acc, __ldg(hopwise + hop), out);
}

// ---------------- launch -----------------------------------------------------
extern "C" void kernel_launch(void* const* d_in, const int* in_sizes, int n_in,
                              void* d_out, int out_size) {
    const float* x  = (const float*)d_in[0];
    const int*   ei = (const int*)d_in[1];
    const float* ef = (const float*)d_in[2];
    const float* ew = (const float*)d_in[3];
    const float* Wq = (const float*)d_in[4];
    const float* bq = (const float*)d_in[5];
    const float* Wk = (const float*)d_in[6];
    const float* bk = (const float*)d_in[7];
    const float* Wv = (const float*)d_in[8];
    const float* bv = (const float*)d_in[9];
    const float* hw = (const float*)d_in[10];
    const int* row = ei;
    const int* col = ei + EE;
    float* out = (float*)d_out;

    uint4 *dMA, *dMB;
    void* dcnt;
    cudaGetSymbolAddress((void**)&dMA, g_MA4);
    cudaGetSymbolAddress((void**)&dMB, g_MB4);
    cudaGetSymbolAddress(&dcnt, g_cnt);

    cudaMemsetAsync(dcnt, 0, NN * sizeof(int));
    k_count<<<(EE + 255) / 256, 256>>>(col);
    k_scan<<<1, 1024>>>();
    k_place<<<(EE + 255) / 256, 256>>>(col);

    k_qkv<<<NN / 40, 256>>>(x, Wq, bq, Wk, bk, Wv, bv, hw, out);

    k_hop0<<<2500, 256>>>(row, ew, ef, hw, out);         // sort+gather+hop0 -> MA
    k_prop<<<2500, 256>>>(dMA, dMB, 1, 2, hw, out);      // MA -> MB
    k_prop<<<2500, 256>>>(dMB, dMA, 0, 3, hw, out);      // MB read-only
}

// round 12
// speedup vs baseline: 1.0164x; 1.0164x over previous
#include <cuda_runtime.h>
#include <cuda_fp16.h>
#include <math.h>

#define NN 10000
#define EE 160000

// ---------------- scratch (device globals; no allocations allowed) ----------
__device__ float g_Q[NN * 64];
__device__ float g_K[NN * 64];
__device__ float g_V[NN * 64];
__device__ uint4 g_MA4[NN * 64];   // NN x 512 halfs
__device__ uint4 g_MB4[NN * 64];
__device__ float g_deginv[NN];
__device__ int   g_cnt[NN];
__device__ int   g_ptr[NN + 1];
__device__ int   g_wp[NN];
__device__ int   g_eidx[EE];   // bucketed (unsorted) edge ids from k_place
__device__ int   g_src[EE];    // sorted-position source node (written by hop0)
__device__ float g_wt[EE];     // sorted-position norm weight (written by hop0)

// ---------------- setup ------------------------------------------------------
__global__ void k_count(const int* __restrict__ col) {
    int e = blockIdx.x * blockDim.x + threadIdx.x;
    if (e < EE) atomicAdd(&g_cnt[col[e]], 1);
}

// single-block exclusive scan of g_cnt -> g_ptr / g_wp ; also deginv
__global__ void k_scan() {
    __shared__ int s[1024];
    int t = threadIdx.x;
    const int CH = (NN + 1023) / 1024;
    int start = t * CH;
    int sum = 0;
    for (int i = 0; i < CH; i++) {
        int idx = start + i;
        if (idx < NN) sum += g_cnt[idx];
    }
    s[t] = sum;
    __syncthreads();
    for (int off = 1; off < 1024; off <<= 1) {
        int v = (t >= off) ? s[t - off] : 0;
        __syncthreads();
        s[t] += v;
        __syncthreads();
    }
    int run = (t == 0) ? 0 : s[t - 1];
    for (int i = 0; i < CH; i++) {
        int idx = start + i;
        if (idx < NN) {
            int c = g_cnt[idx];
            g_ptr[idx] = run;
            g_wp[idx]  = run;
            g_deginv[idx] = (c > 0) ? rsqrtf((float)c) : 0.0f;
            run += c;
        }
    }
    if (t == 0) g_ptr[NN] = s[1023];
}

__global__ void k_place(const int* __restrict__ col) {
    int e = blockIdx.x * blockDim.x + threadIdx.x;
    if (e < EE) {
        int c = col[e];
        int p = atomicAdd(&g_wp[c], 1);
        g_eidx[p] = e;
    }
}

// ---------------- Q/K/V GEMM + hidden init ----------------------------------
// 16 nodes/block (grid 625), 256 threads; thread owns col c x 4 nodes.
// sx stride padded to 68 floats: the 4 node-addresses per k hit DISTINCT banks
// (68 mod 32 = 4) and stay 16B-aligned -> conflict-free LDS.128 broadcasts.
#define XS 68
__global__ void __launch_bounds__(256) k_qkv(const float* __restrict__ x,
                      const float* __restrict__ Wq, const float* __restrict__ bq,
                      const float* __restrict__ Wk, const float* __restrict__ bk,
                      const float* __restrict__ Wv, const float* __restrict__ bv,
                      const float* __restrict__ hopwise, float* __restrict__ out) {
    __shared__ float sx[16 * XS];
    int n0 = blockIdx.x * 16;
    for (int idx = threadIdx.x; idx < 16 * 64; idx += 256)
        sx[(idx >> 6) * XS + (idx & 63)] = x[(n0 + (idx >> 6)) * 64 + (idx & 63)];

    int c = threadIdx.x & 63;
    int g = threadIdx.x >> 6;  // 0..3
    float hw0 = __ldg(hopwise);
    float bqc = __ldg(bq + c), bkc = __ldg(bk + c), bvc = __ldg(bv + c);
    __syncthreads();

    float aq[4] = {0, 0, 0, 0}, ak[4] = {0, 0, 0, 0}, av[4] = {0, 0, 0, 0};

#pragma unroll 4
    for (int k0 = 0; k0 < 64; k0 += 4) {
        float4 xr[4];
#pragma unroll
        for (int p = 0; p < 4; p++)
            xr[p] = *(const float4*)(sx + (g + 4 * p) * XS + k0);
#pragma unroll
        for (int kk = 0; kk < 4; kk++) {
            float wq = __ldg(Wq + (k0 + kk) * 64 + c);
            float wk = __ldg(Wk + (k0 + kk) * 64 + c);
            float wv = __ldg(Wv + (k0 + kk) * 64 + c);
#pragma unroll
            for (int p = 0; p < 4; p++) {
                float xv = ((const float*)&xr[p])[kk];
                aq[p] += xv * wq;
                ak[p] += xv * wk;
                av[p] += xv * wv;
            }
        }
    }
#pragma unroll
    for (int p = 0; p < 4; p++) {
        int n = n0 + g + 4 * p;
        g_Q[n * 64 + c] = fmaxf(aq[p] + bqc, 0.0f);
        g_K[n * 64 + c] = ak[p] + bkc;
        float v = av[p] + bvc;
        g_V[n * 64 + c] = v;
        out[n * 64 + c] = hw0 * v;
    }
}

// ---------------- fused epilogue (64 threads/node) ---------------------------
__device__ __forceinline__ void h_epilogue64(int n, int t, const float* acc,
                                             float hw, float* __restrict__ out) {
    float q = g_Q[n * 64 + t];
    float Hp[8];
#pragma unroll
    for (int j = 0; j < 8; j++) Hp[j] = q * acc[j];
#pragma unroll
    for (int off = 1; off < 8; off <<= 1) {
#pragma unroll
        for (int j = 0; j < 8; j++)
            Hp[j] += __shfl_xor_sync(0xffffffffu, Hp[j], off);
    }
    if ((t & 7) == 0) {
        float ss = 0.f;
#pragma unroll
        for (int j = 0; j < 8; j++) ss += Hp[j] * Hp[j];
        float nrm = sqrtf(ss * 0.125f);
        float sc = (nrm > 1.0f) ? (1.0f / nrm) : 1.0f;
        float c = hw * sc;
        int h = t >> 3;
        float4* op = (float4*)(out + n * 64 + h * 8);
        float4 o0 = op[0], o1 = op[1];
        o0.x += c * Hp[0]; o0.y += c * Hp[1]; o0.z += c * Hp[2]; o0.w += c * Hp[3];
        o1.x += c * Hp[4]; o1.y += c * Hp[5]; o1.z += c * Hp[6]; o1.w += c * Hp[7];
        op[0] = o0; op[1] = o1;
    }
}

__device__ __forceinline__ void acc8(float* a, uint4 A, float w) {
    const __half2* h = (const __half2*)&A;
#pragma unroll
    for (int q = 0; q < 4; q++) {
        float2 f = __half22float2(h[q]);
        a[2 * q]     += w * f.x;
        a[2 * q + 1] += w * f.y;
    }
}

__device__ __forceinline__ uint4 pack8(const float* a) {
    uint4 o;
    __half2* ho = (__half2*)&o;
#pragma unroll
    for (int q = 0; q < 4; q++)
        ho[q] = __float22half2_rn(make_float2(a[2 * q], a[2 * q + 1]));
    return o;
}

// ---------------- hop 0: sort buckets + outer product + fused H-update -------
__global__ void __launch_bounds__(256) k_hop0(const int* __restrict__ row,
                                              const float* __restrict__ ew,
                                              const float* __restrict__ ef,
                                              const float* __restrict__ hopwise,
                                              float* __restrict__ out) {
    __shared__ int   s_e[4][128];
    __shared__ int   s_r[4][128];
    __shared__ float s_w[4][128];
    __shared__ int   s_glob[4];

    int warp = threadIdx.x >> 5;
    int lane = threadIdx.x & 31;
    int ln   = warp >> 1;                 // local node 0..3
    int node = blockIdx.x * 4 + ln;       // NN divisible by 4
    int b = g_ptr[node], e2 = g_ptr[node + 1];
    int d = e2 - b;

    if ((warp & 1) == 0) {                // even warp: sort + metadata
        if (lane == 0) s_glob[ln] = 0;
        float dc = g_deginv[node];
        if (d > 0 && d <= 32) {
            int v = (lane < d) ? g_eidx[b + lane] : 0x7fffffff;
#pragma unroll
            for (int k = 2; k <= 32; k <<= 1) {
#pragma unroll
                for (int j = k >> 1; j > 0; j >>= 1) {
                    int other = __shfl_xor_sync(0xffffffffu, v, j);
                    bool higher = (lane & j) != 0;
                    bool asc = (lane & k) == 0;
                    v = (higher == asc) ? max(v, other) : min(v, other);
                }
            }
            if (lane < d) {
                int r = __ldg(row + v);
                float w = g_deginv[r] * dc * __ldg(ew + v);
                s_e[ln][lane] = v;
                s_r[ln][lane] = r;
                s_w[ln][lane] = w;
                g_src[b + lane] = r;
                g_wt[b + lane]  = w;
            }
        } else if (d > 32 && d <= 128) {
            for (int i = lane; i < d; i += 32) s_e[ln][i] = g_eidx[b + i];
            __syncwarp();
            for (int ph = 0; ph < d; ph++) {
                int startp = ph & 1;
                for (int i = startp + 2 * lane; i + 1 < d; i += 64) {
                    int a = s_e[ln][i], c = s_e[ln][i + 1];
                    if (a > c) { s_e[ln][i] = c; s_e[ln][i + 1] = a; }
                }
                __syncwarp();
            }
            for (int i = lane; i < d; i += 32) {
                int e = s_e[ln][i];
                int r = __ldg(row + e);
                float w = g_deginv[r] * dc * __ldg(ew + e);
                s_r[ln][i] = r;
                s_w[ln][i] = w;
                g_src[b + i] = r;
                g_wt[b + i]  = w;
            }
        } else if (d > 128) {
            if (lane == 0) {
                s_glob[ln] = 1;
                for (int i = b + 1; i < e2; i++) {
                    int v = g_eidx[i];
                    int j = i - 1;
                    while (j >= b && g_eidx[j] > v) {
                        g_eidx[j + 1] = g_eidx[j];
                        j--;
                    }
                    g_eidx[j + 1] = v;
                }
            }
            __syncwarp();
            for (int i = b + lane; i < e2; i += 32) {
                int e = g_eidx[i];
                int r = __ldg(row + e);
                g_src[i] = r;
                g_wt[i]  = g_deginv[r] * dc * __ldg(ew + e);
            }
        }
    }
    __syncthreads();

    int t = threadIdx.x & 63;
    int h8 = (t >> 3) << 3;
    float acc[8];
#pragma unroll
    for (int j = 0; j < 8; j++) acc[j] = 0.0f;

    if (!s_glob[ln]) {
        int p = 0;
        for (; p + 4 <= d; p += 4) {
            float kv[4], fv[4], w[4];
            float4 va[4], vb[4];
#pragma unroll
            for (int q = 0; q < 4; q++) {
                int e = s_e[ln][p + q];
                int r = s_r[ln][p + q];
                w[q]  = s_w[ln][p + q];
                kv[q] = g_K[r * 64 + t];
                fv[q] = ef[(size_t)e * 64 + t];
                va[q] = *(const float4*)(g_V + r * 64 + h8);
                vb[q] = *(const float4*)(g_V + r * 64 + h8 + 4);
            }
#pragma unroll
            for (int q = 0; q < 4; q++) {
                float a = fmaxf(kv[q] + fv[q], 0.0f) * w[q];
                acc[0] += a * va[q].x; acc[1] += a * va[q].y;
                acc[2] += a * va[q].z; acc[3] += a * va[q].w;
                acc[4] += a * vb[q].x; acc[5] += a * vb[q].y;
                acc[6] += a * vb[q].z; acc[7] += a * vb[q].w;
            }
        }
        for (; p < d; p++) {
            int e = s_e[ln][p];
            int r = s_r[ln][p];
            float w0 = s_w[ln][p];
            float kv = g_K[r * 64 + t];
            float fv = ef[(size_t)e * 64 + t];
            float4 va = *(const float4*)(g_V + r * 64 + h8);
            float4 vb = *(const float4*)(g_V + r * 64 + h8 + 4);
            float a = fmaxf(kv + fv, 0.0f) * w0;
            acc[0] += a * va.x; acc[1] += a * va.y; acc[2] += a * va.z; acc[3] += a * va.w;
            acc[4] += a * vb.x; acc[5] += a * vb.y; acc[6] += a * vb.z; acc[7] += a * vb.w;
        }
    } else {
        for (int p = b; p < e2; p++) {
            int e = g_eidx[p];
            int r = g_src[p];
            float w0 = g_wt[p];
            float kv = g_K[r * 64 + t];
            float fv = ef[(size_t)e * 64 + t];
            float4 va = *(const float4*)(g_V + r * 64 + h8);
            float4 vb = *(const float4*)(g_V + r * 64 + h8 + 4);
            float a = fmaxf(kv + fv, 0.0f) * w0;
            acc[0] += a * va.x; acc[1] += a * va.y; acc[2] += a * va.z; acc[3] += a * va.w;
            acc[4] += a * vb.x; acc[5] += a * vb.y; acc[6] += a * vb.z; acc[7] += a * vb.w;
        }
    }

    g_MA4[(size_t)node * 64 + t] = pack8(acc);
    h_epilogue64(node, t, acc, __ldg(hopwise + 1), out);
}

// ---------------- prop hops + fused H-update (64 threads/node) ---------------
__global__ void __launch_bounds__(256) k_prop(const uint4* __restrict__ Msrc,
                                              uint4* __restrict__ Mdst, int writeM,
                                              int hop, const float* __restrict__ hopwise,
                                              float* __restrict__ out) {
    int node = blockIdx.x * 4 + (threadIdx.x >> 6);
    if (node >= NN) return;
    int t = threadIdx.x & 63;

    float acc[8];
#pragma unroll
    for (int j = 0; j < 8; j++) acc[j] = 0.0f;

    int beg = g_ptr[node], end = g_ptr[node + 1];
    int p = beg;
    for (; p + 8 <= end; p += 8) {
        uint4 A[8];
        float w[8];
#pragma unroll
        for (int q = 0; q < 8; q++) {
            int r = g_src[p + q];
            w[q] = g_wt[p + q];
            A[q] = Msrc[(size_t)r * 64 + t];
        }
#pragma unroll
        for (int q = 0; q < 8; q++) acc8(acc, A[q], w[q]);
    }
    for (; p + 4 <= end; p += 4) {
        uint4 A[4];
        float w[4];
#pragma unroll
        for (int q = 0; q < 4; q++) {
            int r = g_src[p + q];
            w[q] = g_wt[p + q];
            A[q] = Msrc[(size_t)r * 64 + t];
        }
#pragma unroll
        for (int q = 0; q < 4; q++) acc8(acc, A[q], w[q]);
    }
    for (; p < end; p++) {
        int r = g_src[p];
        float w0 = g_wt[p];
        uint4 A = Msrc[(size_t)r * 64 + t];
        acc8(acc, A, w0);
    }

    if (writeM) Mdst[(size_t)node * 64 + t] = pack8(acc);
    h_epilogue64(node, t, acc, __ldg(hopwise + hop), out);
}

// ---------------- launch -----------------------------------------------------
extern "C" void kernel_launch(void* const* d_in, const int* in_sizes, int n_in,
                              void* d_out, int out_size) {
    const float* x  = (const float*)d_in[0];
    const int*   ei = (const int*)d_in[1];
    const float* ef = (const float*)d_in[2];
    const float* ew = (const float*)d_in[3];
    const float* Wq = (const float*)d_in[4];
    const float* bq = (const float*)d_in[5];
    const float* Wk = (const float*)d_in[6];
    const float* bk = (const float*)d_in[7];
    const float* Wv = (const float*)d_in[8];
    const float* bv = (const float*)d_in[9];
    const float* hw = (const float*)d_in[10];
    const int* row = ei;
    const int* col = ei + EE;
    float* out = (float*)d_out;

    uint4 *dMA, *dMB;
    void* dcnt;
    cudaGetSymbolAddress((void**)&dMA, g_MA4);
    cudaGetSymbolAddress((void**)&dMB, g_MB4);
    cudaGetSymbolAddress(&dcnt, g_cnt);

    cudaMemsetAsync(dcnt, 0, NN * sizeof(int));
    k_count<<<(EE + 255) / 256, 256>>>(col);
    k_scan<<<1, 1024>>>();
    k_place<<<(EE + 255) / 256, 256>>>(col);

    k_qkv<<<NN / 16, 256>>>(x, Wq, bq, Wk, bk, Wv, bv, hw, out);

    k_hop0<<<2500, 256>>>(row, ew, ef, hw, out);         // sort+gather+hop0 -> MA
    k_prop<<<2500, 256>>>(dMA, dMB, 1, 2, hw, out);      // MA -> MB
    k_prop<<<2500, 256>>>(dMB, dMA, 0, 3, hw, out);      // MB read-only
}

// round 13
// speedup vs baseline: 1.0706x; 1.0533x over previous
#include <cuda_runtime.h>
#include <cuda_fp16.h>
#include <math.h>

#define NN 10000
#define EE 160000

// ---------------- scratch (device globals; no allocations allowed) ----------
__device__ float g_Q[NN * 64];
__device__ float g_K[NN * 64];
__device__ float g_V[NN * 64];
__device__ uint4 g_MA4[NN * 64];   // NN x 512 halfs
__device__ uint4 g_MB4[NN * 64];
__device__ float g_deginv[NN];
__device__ int   g_cnt[NN];
__device__ int   g_ptr[NN + 1];
__device__ int   g_wp[NN];
__device__ int   g_order[NN];  // nodes in descending-degree order
__device__ int   g_eidx[EE];   // bucketed (unsorted) edge ids from k_place
__device__ int   g_src[EE];    // sorted-position source node (written by hop0)
__device__ float g_wt[EE];     // sorted-position norm weight (written by hop0)

// ---------------- fused count + Q/K/V GEMM -----------------------------------
// blocks [0,625): degree count (atomic). blocks [625,1250): qkv GEMM.
// Independent work items co-resident so qkv warps fill count's atomic stalls.
#define XS 68
__global__ void __launch_bounds__(256) k_count_qkv(
                      const int* __restrict__ col,
                      const float* __restrict__ x,
                      const float* __restrict__ Wq, const float* __restrict__ bq,
                      const float* __restrict__ Wk, const float* __restrict__ bk,
                      const float* __restrict__ Wv, const float* __restrict__ bv,
                      const float* __restrict__ hopwise, float* __restrict__ out) {
    if (blockIdx.x < 625) {
        int e = blockIdx.x * 256 + threadIdx.x;
        if (e < EE) atomicAdd(&g_cnt[col[e]], 1);
        return;
    }
    __shared__ float sx[16 * XS];
    int bi = blockIdx.x - 625;
    int n0 = bi * 16;
    for (int idx = threadIdx.x; idx < 16 * 64; idx += 256)
        sx[(idx >> 6) * XS + (idx & 63)] = x[(n0 + (idx >> 6)) * 64 + (idx & 63)];

    int c = threadIdx.x & 63;
    int g = threadIdx.x >> 6;  // 0..3
    float hw0 = __ldg(hopwise);
    float bqc = __ldg(bq + c), bkc = __ldg(bk + c), bvc = __ldg(bv + c);
    __syncthreads();

    float aq[4] = {0, 0, 0, 0}, ak[4] = {0, 0, 0, 0}, av[4] = {0, 0, 0, 0};

#pragma unroll 4
    for (int k0 = 0; k0 < 64; k0 += 4) {
        float4 xr[4];
#pragma unroll
        for (int p = 0; p < 4; p++)
            xr[p] = *(const float4*)(sx + (g + 4 * p) * XS + k0);
#pragma unroll
        for (int kk = 0; kk < 4; kk++) {
            float wq = __ldg(Wq + (k0 + kk) * 64 + c);
            float wk = __ldg(Wk + (k0 + kk) * 64 + c);
            float wv = __ldg(Wv + (k0 + kk) * 64 + c);
#pragma unroll
            for (int p = 0; p < 4; p++) {
                float xv = ((const float*)&xr[p])[kk];
                aq[p] += xv * wq;
                ak[p] += xv * wk;
                av[p] += xv * wv;
            }
        }
    }
#pragma unroll
    for (int p = 0; p < 4; p++) {
        int n = n0 + g + 4 * p;
        g_Q[n * 64 + c] = fmaxf(aq[p] + bqc, 0.0f);
        g_K[n * 64 + c] = ak[p] + bkc;
        float v = av[p] + bvc;
        g_V[n * 64 + c] = v;
        out[n * 64 + c] = hw0 * v;
    }
}

// single-block: exclusive scan of g_cnt -> g_ptr/g_wp, deginv, and
// descending-degree node ordering (g_order). Node order within a degree bin is
// arbitrary but output-irrelevant: per-node results are independent and the
// per-node EDGE order stays sorted, so outputs remain deterministic.
__global__ void k_scan() {
    __shared__ int s[1024];
    __shared__ int hist[256];
    __shared__ int off[256];
    int t = threadIdx.x;
    const int CH = (NN + 1023) / 1024;  // 10
    int start = t * CH;
    int sum = 0;
    for (int i = 0; i < CH; i++) {
        int idx = start + i;
        if (idx < NN) sum += g_cnt[idx];
    }
    s[t] = sum;
    __syncthreads();
    for (int off2 = 1; off2 < 1024; off2 <<= 1) {
        int v = (t >= off2) ? s[t - off2] : 0;
        __syncthreads();
        s[t] += v;
        __syncthreads();
    }
    int run = (t == 0) ? 0 : s[t - 1];
    for (int i = 0; i < CH; i++) {
        int idx = start + i;
        if (idx < NN) {
            int c = g_cnt[idx];
            g_ptr[idx] = run;
            g_wp[idx]  = run;
            g_deginv[idx] = (c > 0) ? rsqrtf((float)c) : 0.0f;
            run += c;
        }
    }
    if (t == 0) g_ptr[NN] = s[1023];

    // degree histogram (clamped to 255)
    if (t < 256) hist[t] = 0;
    __syncthreads();
    for (int i = 0; i < CH; i++) {
        int idx = start + i;
        if (idx < NN) atomicAdd(&hist[min(g_cnt[idx], 255)], 1);
    }
    __syncthreads();
    if (t == 0) {
        int r2 = 0;
        for (int d = 255; d >= 0; d--) { off[d] = r2; r2 += hist[d]; }
    }
    __syncthreads();
    if (t < 256) hist[t] = 0;   // reuse as per-bin cursor
    __syncthreads();
    for (int i = 0; i < CH; i++) {
        int idx = start + i;
        if (idx < NN) {
            int d = min(g_cnt[idx], 255);
            int r = atomicAdd(&hist[d], 1);
            g_order[off[d] + r] = idx;
        }
    }
}

__global__ void k_place(const int* __restrict__ col) {
    int e = blockIdx.x * blockDim.x + threadIdx.x;
    if (e < EE) {
        int c = col[e];
        int p = atomicAdd(&g_wp[c], 1);
        g_eidx[p] = e;
    }
}

// ---------------- fused epilogue (64 threads/node) ---------------------------
__device__ __forceinline__ void h_epilogue64(int n, int t, const float* acc,
                                             float hw, float* __restrict__ out) {
    float q = g_Q[n * 64 + t];
    float Hp[8];
#pragma unroll
    for (int j = 0; j < 8; j++) Hp[j] = q * acc[j];
#pragma unroll
    for (int off = 1; off < 8; off <<= 1) {
#pragma unroll
        for (int j = 0; j < 8; j++)
            Hp[j] += __shfl_xor_sync(0xffffffffu, Hp[j], off);
    }
    if ((t & 7) == 0) {
        float ss = 0.f;
#pragma unroll
        for (int j = 0; j < 8; j++) ss += Hp[j] * Hp[j];
        float nrm = sqrtf(ss * 0.125f);
        float sc = (nrm > 1.0f) ? (1.0f / nrm) : 1.0f;
        float c = hw * sc;
        int h = t >> 3;
        float4* op = (float4*)(out + n * 64 + h * 8);
        float4 o0 = op[0], o1 = op[1];
        o0.x += c * Hp[0]; o0.y += c * Hp[1]; o0.z += c * Hp[2]; o0.w += c * Hp[3];
        o1.x += c * Hp[4]; o1.y += c * Hp[5]; o1.z += c * Hp[6]; o1.w += c * Hp[7];
        op[0] = o0; op[1] = o1;
    }
}

__device__ __forceinline__ void acc8(float* a, uint4 A, float w) {
    const __half2* h = (const __half2*)&A;
#pragma unroll
    for (int q = 0; q < 4; q++) {
        float2 f = __half22float2(h[q]);
        a[2 * q]     += w * f.x;
        a[2 * q + 1] += w * f.y;
    }
}

__device__ __forceinline__ uint4 pack8(const float* a) {
    uint4 o;
    __half2* ho = (__half2*)&o;
#pragma unroll
    for (int q = 0; q < 4; q++)
        ho[q] = __float22half2_rn(make_float2(a[2 * q], a[2 * q + 1]));
    return o;
}

// ---------------- hop 0: sort buckets + outer product + fused H-update -------
__global__ void __launch_bounds__(256) k_hop0(const int* __restrict__ row,
                                              const float* __restrict__ ew,
                                              const float* __restrict__ ef,
                                              const float* __restrict__ hopwise,
                                              float* __restrict__ out) {
    __shared__ int   s_e[4][128];
    __shared__ int   s_r[4][128];
    __shared__ float s_w[4][128];
    __shared__ int   s_glob[4];

    int warp = threadIdx.x >> 5;
    int lane = threadIdx.x & 31;
    int ln   = warp >> 1;                 // local node 0..3
    int node = g_order[blockIdx.x * 4 + ln];
    int b = g_ptr[node], e2 = g_ptr[node + 1];
    int d = e2 - b;

    if ((warp & 1) == 0) {                // even warp: sort + metadata
        if (lane == 0) s_glob[ln] = 0;
        float dc = g_deginv[node];
        if (d > 0 && d <= 32) {
            int v = (lane < d) ? g_eidx[b + lane] : 0x7fffffff;
#pragma unroll
            for (int k = 2; k <= 32; k <<= 1) {
#pragma unroll
                for (int j = k >> 1; j > 0; j >>= 1) {
                    int other = __shfl_xor_sync(0xffffffffu, v, j);
                    bool higher = (lane & j) != 0;
                    bool asc = (lane & k) == 0;
                    v = (higher == asc) ? max(v, other) : min(v, other);
                }
            }
            if (lane < d) {
                int r = __ldg(row + v);
                float w = g_deginv[r] * dc * __ldg(ew + v);
                s_e[ln][lane] = v;
                s_r[ln][lane] = r;
                s_w[ln][lane] = w;
                g_src[b + lane] = r;
                g_wt[b + lane]  = w;
            }
        } else if (d > 32 && d <= 128) {
            for (int i = lane; i < d; i += 32) s_e[ln][i] = g_eidx[b + i];
            __syncwarp();
            for (int ph = 0; ph < d; ph++) {
                int startp = ph & 1;
                for (int i = startp + 2 * lane; i + 1 < d; i += 64) {
                    int a = s_e[ln][i], c = s_e[ln][i + 1];
                    if (a > c) { s_e[ln][i] = c; s_e[ln][i + 1] = a; }
                }
                __syncwarp();
            }
            for (int i = lane; i < d; i += 32) {
                int e = s_e[ln][i];
                int r = __ldg(row + e);
                float w = g_deginv[r] * dc * __ldg(ew + e);
                s_r[ln][i] = r;
                s_w[ln][i] = w;
                g_src[b + i] = r;
                g_wt[b + i]  = w;
            }
        } else if (d > 128) {
            if (lane == 0) {
                s_glob[ln] = 1;
                for (int i = b + 1; i < e2; i++) {
                    int v = g_eidx[i];
                    int j = i - 1;
                    while (j >= b && g_eidx[j] > v) {
                        g_eidx[j + 1] = g_eidx[j];
                        j--;
                    }
                    g_eidx[j + 1] = v;
                }
            }
            __syncwarp();
            for (int i = b + lane; i < e2; i += 32) {
                int e = g_eidx[i];
                int r = __ldg(row + e);
                g_src[i] = r;
                g_wt[i]  = g_deginv[r] * dc * __ldg(ew + e);
            }
        }
    }
    __syncthreads();

    int t = threadIdx.x & 63;
    int h8 = (t >> 3) << 3;
    float acc[8];
#pragma unroll
    for (int j = 0; j < 8; j++) acc[j] = 0.0f;

    if (!s_glob[ln]) {
        int p = 0;
        for (; p + 4 <= d; p += 4) {
            float kv[4], fv[4], w[4];
            float4 va[4], vb[4];
#pragma unroll
            for (int q = 0; q < 4; q++) {
                int e = s_e[ln][p + q];
                int r = s_r[ln][p + q];
                w[q]  = s_w[ln][p + q];
                kv[q] = g_K[r * 64 + t];
                fv[q] = ef[(size_t)e * 64 + t];
                va[q] = *(const float4*)(g_V + r * 64 + h8);
                vb[q] = *(const float4*)(g_V + r * 64 + h8 + 4);
            }
#pragma unroll
            for (int q = 0; q < 4; q++) {
                float a = fmaxf(kv[q] + fv[q], 0.0f) * w[q];
                acc[0] += a * va[q].x; acc[1] += a * va[q].y;
                acc[2] += a * va[q].z; acc[3] += a * va[q].w;
                acc[4] += a * vb[q].x; acc[5] += a * vb[q].y;
                acc[6] += a * vb[q].z; acc[7] += a * vb[q].w;
            }
        }
        for (; p < d; p++) {
            int e = s_e[ln][p];
            int r = s_r[ln][p];
            float w0 = s_w[ln][p];
            float kv = g_K[r * 64 + t];
            float fv = ef[(size_t)e * 64 + t];
            float4 va = *(const float4*)(g_V + r * 64 + h8);
            float4 vb = *(const float4*)(g_V + r * 64 + h8 + 4);
            float a = fmaxf(kv + fv, 0.0f) * w0;
            acc[0] += a * va.x; acc[1] += a * va.y; acc[2] += a * va.z; acc[3] += a * va.w;
            acc[4] += a * vb.x; acc[5] += a * vb.y; acc[6] += a * vb.z; acc[7] += a * vb.w;
        }
    } else {
        for (int p = b; p < e2; p++) {
            int e = g_eidx[p];
            int r = g_src[p];
            float w0 = g_wt[p];
            float kv = g_K[r * 64 + t];
            float fv = ef[(size_t)e * 64 + t];
            float4 va = *(const float4*)(g_V + r * 64 + h8);
            float4 vb = *(const float4*)(g_V + r * 64 + h8 + 4);
            float a = fmaxf(kv + fv, 0.0f) * w0;
            acc[0] += a * va.x; acc[1] += a * va.y; acc[2] += a * va.z; acc[3] += a * va.w;
            acc[4] += a * vb.x; acc[5] += a * vb.y; acc[6] += a * vb.z; acc[7] += a * vb.w;
        }
    }

    g_MA4[(size_t)node * 64 + t] = pack8(acc);
    h_epilogue64(node, t, acc, __ldg(hopwise + 1), out);
}

// ---------------- prop hops + fused H-update (64 threads/node) ---------------
__global__ void __launch_bounds__(256) k_prop(const uint4* __restrict__ Msrc,
                                              uint4* __restrict__ Mdst, int writeM,
                                              int hop, const float* __restrict__ hopwise,
                                              float* __restrict__ out) {
    int node = g_order[blockIdx.x * 4 + (threadIdx.x >> 6)];
    int t = threadIdx.x & 63;

    float acc[8];
#pragma unroll
    for (int j = 0; j < 8; j++) acc[j] = 0.0f;

    int beg = g_ptr[node], end = g_ptr[node + 1];
    int p = beg;
    for (; p + 8 <= end; p += 8) {
        uint4 A[8];
        float w[8];
#pragma unroll
        for (int q = 0; q < 8; q++) {
            int r = g_src[p + q];
            w[q] = g_wt[p + q];
            A[q] = Msrc[(size_t)r * 64 + t];
        }
#pragma unroll
        for (int q = 0; q < 8; q++) acc8(acc, A[q], w[q]);
    }
    for (; p + 4 <= end; p += 4) {
        uint4 A[4];
        float w[4];
#pragma unroll
        for (int q = 0; q < 4; q++) {
            int r = g_src[p + q];
            w[q] = g_wt[p + q];
            A[q] = Msrc[(size_t)r * 64 + t];
        }
#pragma unroll
        for (int q = 0; q < 4; q++) acc8(acc, A[q], w[q]);
    }
    for (; p < end; p++) {
        int r = g_src[p];
        float w0 = g_wt[p];
        uint4 A = Msrc[(size_t)r * 64 + t];
        acc8(acc, A, w0);
    }

    if (writeM) Mdst[(size_t)node * 64 + t] = pack8(acc);
    h_epilogue64(node, t, acc, __ldg(hopwise + hop), out);
}

// ---------------- launch -----------------------------------------------------
extern "C" void kernel_launch(void* const* d_in, const int* in_sizes, int n_in,
                              void* d_out, int out_size) {
    const float* x  = (const float*)d_in[0];
    const int*   ei = (const int*)d_in[1];
    const float* ef = (const float*)d_in[2];
    const float* ew = (const float*)d_in[3];
    const float* Wq = (const float*)d_in[4];
    const float* bq = (const float*)d_in[5];
    const float* Wk = (const float*)d_in[6];
    const float* bk = (const float*)d_in[7];
    const float* Wv = (const float*)d_in[8];
    const float* bv = (const float*)d_in[9];
    const float* hw = (const float*)d_in[10];
    const int* row = ei;
    const int* col = ei + EE;
    float* out = (float*)d_out;

    uint4 *dMA, *dMB;
    void* dcnt;
    cudaGetSymbolAddress((void**)&dMA, g_MA4);
    cudaGetSymbolAddress((void**)&dMB, g_MB4);
    cudaGetSymbolAddress(&dcnt, g_cnt);

    cudaMemsetAsync(dcnt, 0, NN * sizeof(int));
    k_count_qkv<<<1250, 256>>>(col, x, Wq, bq, Wk, bk, Wv, bv, hw, out);
    k_scan<<<1, 1024>>>();
    k_place<<<(EE + 255) / 256, 256>>>(col);

    k_hop0<<<2500, 256>>>(row, ew, ef, hw, out);         // sort+gather+hop0 -> MA
    k_prop<<<2500, 256>>>(dMA, dMB, 1, 2, hw, out);      // MA -> MB
    k_prop<<<2500, 256>>>(dMB, dMA, 0, 3, hw, out);      // MB read-only
}

// round 14
// speedup vs baseline: 1.0891x; 1.0173x over previous
#include <cuda_runtime.h>
#include <cuda_fp16.h>
#include <math.h>

#define NN 10000
#define EE 160000

// ---------------- scratch (device globals; no allocations allowed) ----------
__device__ float g_Q[NN * 64];
__device__ float g_K[NN * 64];
__device__ float g_V[NN * 64];
__device__ uint4 g_MA4[NN * 64];   // NN x 512 halfs
__device__ uint4 g_MB4[NN * 64];
__device__ float g_deginv[NN];
__device__ int   g_cnt[NN];
__device__ int   g_ptr[NN + 1];
__device__ int   g_wp[NN];
__device__ int   g_order[NN];  // nodes in descending-degree order
__device__ int   g_eidx[EE];   // bucketed edge ids (sorted within bucket by hop0)
__device__ int2  g_meta[EE];   // per sorted slot: {src node, norm weight bits}

// ---------------- fused count + Q/K/V GEMM -----------------------------------
#define XS 68
__global__ void __launch_bounds__(256) k_count_qkv(
                      const int* __restrict__ col,
                      const float* __restrict__ x,
                      const float* __restrict__ Wq, const float* __restrict__ bq,
                      const float* __restrict__ Wk, const float* __restrict__ bk,
                      const float* __restrict__ Wv, const float* __restrict__ bv,
                      const float* __restrict__ hopwise, float* __restrict__ out) {
    if (blockIdx.x < 625) {
        int e = blockIdx.x * 256 + threadIdx.x;
        if (e < EE) atomicAdd(&g_cnt[col[e]], 1);
        return;
    }
    __shared__ float sx[16 * XS];
    int bi = blockIdx.x - 625;
    int n0 = bi * 16;
    for (int idx = threadIdx.x; idx < 16 * 64; idx += 256)
        sx[(idx >> 6) * XS + (idx & 63)] = x[(n0 + (idx >> 6)) * 64 + (idx & 63)];

    int c = threadIdx.x & 63;
    int g = threadIdx.x >> 6;  // 0..3
    float hw0 = __ldg(hopwise);
    float bqc = __ldg(bq + c), bkc = __ldg(bk + c), bvc = __ldg(bv + c);
    __syncthreads();

    float aq[4] = {0, 0, 0, 0}, ak[4] = {0, 0, 0, 0}, av[4] = {0, 0, 0, 0};

#pragma unroll 4
    for (int k0 = 0; k0 < 64; k0 += 4) {
        float4 xr[4];
#pragma unroll
        for (int p = 0; p < 4; p++)
            xr[p] = *(const float4*)(sx + (g + 4 * p) * XS + k0);
#pragma unroll
        for (int kk = 0; kk < 4; kk++) {
            float wq = __ldg(Wq + (k0 + kk) * 64 + c);
            float wk = __ldg(Wk + (k0 + kk) * 64 + c);
            float wv = __ldg(Wv + (k0 + kk) * 64 + c);
#pragma unroll
            for (int p = 0; p < 4; p++) {
                float xv = ((const float*)&xr[p])[kk];
                aq[p] += xv * wq;
                ak[p] += xv * wk;
                av[p] += xv * wv;
            }
        }
    }
#pragma unroll
    for (int p = 0; p < 4; p++) {
        int n = n0 + g + 4 * p;
        g_Q[n * 64 + c] = fmaxf(aq[p] + bqc, 0.0f);
        g_K[n * 64 + c] = ak[p] + bkc;
        float v = av[p] + bvc;
        g_V[n * 64 + c] = v;
        out[n * 64 + c] = hw0 * v;
    }
}

// single-block: scan, deginv, descending-degree node order
__global__ void k_scan() {
    __shared__ int s[1024];
    __shared__ int hist[256];
    __shared__ int off[256];
    int t = threadIdx.x;
    const int CH = (NN + 1023) / 1024;  // 10
    int start = t * CH;
    int sum = 0;
    for (int i = 0; i < CH; i++) {
        int idx = start + i;
        if (idx < NN) sum += g_cnt[idx];
    }
    s[t] = sum;
    __syncthreads();
    for (int off2 = 1; off2 < 1024; off2 <<= 1) {
        int v = (t >= off2) ? s[t - off2] : 0;
        __syncthreads();
        s[t] += v;
        __syncthreads();
    }
    int run = (t == 0) ? 0 : s[t - 1];
    for (int i = 0; i < CH; i++) {
        int idx = start + i;
        if (idx < NN) {
            int c = g_cnt[idx];
            g_ptr[idx] = run;
            g_wp[idx]  = run;
            g_deginv[idx] = (c > 0) ? rsqrtf((float)c) : 0.0f;
            run += c;
        }
    }
    if (t == 0) g_ptr[NN] = s[1023];

    if (t < 256) hist[t] = 0;
    __syncthreads();
    for (int i = 0; i < CH; i++) {
        int idx = start + i;
        if (idx < NN) atomicAdd(&hist[min(g_cnt[idx], 255)], 1);
    }
    __syncthreads();
    if (t == 0) {
        int r2 = 0;
        for (int d = 255; d >= 0; d--) { off[d] = r2; r2 += hist[d]; }
    }
    __syncthreads();
    if (t < 256) hist[t] = 0;
    __syncthreads();
    for (int i = 0; i < CH; i++) {
        int idx = start + i;
        if (idx < NN) {
            int d = min(g_cnt[idx], 255);
            int r = atomicAdd(&hist[d], 1);
            g_order[off[d] + r] = idx;
        }
    }
}

__global__ void k_place(const int* __restrict__ col) {
    int e = blockIdx.x * blockDim.x + threadIdx.x;
    if (e < EE) {
        int c = col[e];
        int p = atomicAdd(&g_wp[c], 1);
        g_eidx[p] = e;
    }
}

// ---------------- fused epilogue (64 threads/node) ---------------------------
__device__ __forceinline__ void h_epilogue64(int n, int t, const float* acc,
                                             float hw, float* __restrict__ out) {
    float q = g_Q[n * 64 + t];
    float Hp[8];
#pragma unroll
    for (int j = 0; j < 8; j++) Hp[j] = q * acc[j];
#pragma unroll
    for (int off = 1; off < 8; off <<= 1) {
#pragma unroll
        for (int j = 0; j < 8; j++)
            Hp[j] += __shfl_xor_sync(0xffffffffu, Hp[j], off);
    }
    if ((t & 7) == 0) {
        float ss = 0.f;
#pragma unroll
        for (int j = 0; j < 8; j++) ss += Hp[j] * Hp[j];
        float nrm = sqrtf(ss * 0.125f);
        float sc = (nrm > 1.0f) ? (1.0f / nrm) : 1.0f;
        float c = hw * sc;
        int h = t >> 3;
        float4* op = (float4*)(out + n * 64 + h * 8);
        float4 o0 = op[0], o1 = op[1];
        o0.x += c * Hp[0]; o0.y += c * Hp[1]; o0.z += c * Hp[2]; o0.w += c * Hp[3];
        o1.x += c * Hp[4]; o1.y += c * Hp[5]; o1.z += c * Hp[6]; o1.w += c * Hp[7];
        op[0] = o0; op[1] = o1;
    }
}

__device__ __forceinline__ void acc8(float* a, uint4 A, float w) {
    const __half2* h = (const __half2*)&A;
#pragma unroll
    for (int q = 0; q < 4; q++) {
        float2 f = __half22float2(h[q]);
        a[2 * q]     += w * f.x;
        a[2 * q + 1] += w * f.y;
    }
}

__device__ __forceinline__ uint4 pack8(const float* a) {
    uint4 o;
    __half2* ho = (__half2*)&o;
#pragma unroll
    for (int q = 0; q < 4; q++)
        ho[q] = __float22half2_rn(make_float2(a[2 * q], a[2 * q + 1]));
    return o;
}

// ---------------- hop 0: sort + parallel gather + outer product + H ----------
// Phase A: even warp sorts its node's bucket (edge ids).
// Phase B: ALL 64 threads of the pair gather r/w (scattered, latency-heavy),
//          fill packed s_m {e,r,wbits} and g_meta {r,wbits}.
// Phase C: compute with 1 broadcast LDS.128 per edge of metadata.
__global__ void __launch_bounds__(256) k_hop0(const int* __restrict__ row,
                                              const float* __restrict__ ew,
                                              const float* __restrict__ ef,
                                              const float* __restrict__ hopwise,
                                              float* __restrict__ out) {
    __shared__ int  s_e[4][128];
    __shared__ int4 s_m[4][128];
    __shared__ int  s_glob[4];

    int warp = threadIdx.x >> 5;
    int lane = threadIdx.x & 31;
    int ln   = warp >> 1;                 // local node 0..3
    int node = g_order[blockIdx.x * 4 + ln];
    int b = g_ptr[node], e2 = g_ptr[node + 1];
    int d = e2 - b;

    // ---- Phase A: sort (even warp only) ----
    if ((warp & 1) == 0) {
        if (lane == 0) s_glob[ln] = (d > 128) ? 1 : 0;
        if (d > 0 && d <= 32) {
            int v = (lane < d) ? g_eidx[b + lane] : 0x7fffffff;
#pragma unroll
            for (int k = 2; k <= 32; k <<= 1) {
#pragma unroll
                for (int j = k >> 1; j > 0; j >>= 1) {
                    int other = __shfl_xor_sync(0xffffffffu, v, j);
                    bool higher = (lane & j) != 0;
                    bool asc = (lane & k) == 0;
                    v = (higher == asc) ? max(v, other) : min(v, other);
                }
            }
            if (lane < d) s_e[ln][lane] = v;
        } else if (d > 32 && d <= 128) {
            for (int i = lane; i < d; i += 32) s_e[ln][i] = g_eidx[b + i];
            __syncwarp();
            for (int ph = 0; ph < d; ph++) {
                int startp = ph & 1;
                for (int i = startp + 2 * lane; i + 1 < d; i += 64) {
                    int a = s_e[ln][i], c = s_e[ln][i + 1];
                    if (a > c) { s_e[ln][i] = c; s_e[ln][i + 1] = a; }
                }
                __syncwarp();
            }
        } else if (d > 128) {
            if (lane == 0) {
                for (int i = b + 1; i < e2; i++) {
                    int v = g_eidx[i];
                    int j = i - 1;
                    while (j >= b && g_eidx[j] > v) {
                        g_eidx[j + 1] = g_eidx[j];
                        j--;
                    }
                    g_eidx[j + 1] = v;
                }
            }
        }
    }
    __syncthreads();

    int t = threadIdx.x & 63;
    int glob = s_glob[ln];
    float dc = g_deginv[node];

    // ---- Phase B: gather with all 64 threads of the pair ----
    if (!glob) {
        if (d <= 32) {
            // sorted ids also need to land back in g_eidx? not needed: compute
            // and prop both read g_meta/s_m; g_eidx only feeds ef addressing via s_m.
            if (t < d) {
                int e = s_e[ln][t];
                int r = __ldg(row + e);
                float w = g_deginv[r] * dc * __ldg(ew + e);
                s_m[ln][t] = make_int4(e, r, __float_as_int(w), 0);
                g_meta[b + t] = make_int2(r, __float_as_int(w));
            }
        } else {
            for (int i = t; i < d; i += 64) {
                int e = s_e[ln][i];
                int r = __ldg(row + e);
                float w = g_deginv[r] * dc * __ldg(ew + e);
                s_m[ln][i] = make_int4(e, r, __float_as_int(w), 0);
                g_meta[b + i] = make_int2(r, __float_as_int(w));
            }
        }
    } else {
        for (int i = t; i < d; i += 64) {
            int e = g_eidx[b + i];
            int r = __ldg(row + e);
            float w = g_deginv[r] * dc * __ldg(ew + e);
            g_meta[b + i] = make_int2(r, __float_as_int(w));
        }
    }
    __syncthreads();

    // ---- Phase C: compute ----
    int h8 = (t >> 3) << 3;
    float acc[8];
#pragma unroll
    for (int j = 0; j < 8; j++) acc[j] = 0.0f;

    if (!glob) {
        int p = 0;
        for (; p + 4 <= d; p += 4) {
            int4 m[4];
            float kv[4], fv[4];
            float4 va[4], vb[4];
#pragma unroll
            for (int q = 0; q < 4; q++) m[q] = s_m[ln][p + q];
#pragma unroll
            for (int q = 0; q < 4; q++) {
                kv[q] = g_K[m[q].y * 64 + t];
                fv[q] = ef[(size_t)m[q].x * 64 + t];
                va[q] = *(const float4*)(g_V + m[q].y * 64 + h8);
                vb[q] = *(const float4*)(g_V + m[q].y * 64 + h8 + 4);
            }
#pragma unroll
            for (int q = 0; q < 4; q++) {
                float a = fmaxf(kv[q] + fv[q], 0.0f) * __int_as_float(m[q].z);
                acc[0] += a * va[q].x; acc[1] += a * va[q].y;
                acc[2] += a * va[q].z; acc[3] += a * va[q].w;
                acc[4] += a * vb[q].x; acc[5] += a * vb[q].y;
                acc[6] += a * vb[q].z; acc[7] += a * vb[q].w;
            }
        }
        for (; p < d; p++) {
            int4 m = s_m[ln][p];
            float kv = g_K[m.y * 64 + t];
            float fv = ef[(size_t)m.x * 64 + t];
            float4 va = *(const float4*)(g_V + m.y * 64 + h8);
            float4 vb = *(const float4*)(g_V + m.y * 64 + h8 + 4);
            float a = fmaxf(kv + fv, 0.0f) * __int_as_float(m.z);
            acc[0] += a * va.x; acc[1] += a * va.y; acc[2] += a * va.z; acc[3] += a * va.w;
            acc[4] += a * vb.x; acc[5] += a * vb.y; acc[6] += a * vb.z; acc[7] += a * vb.w;
        }
    } else {
        for (int p = b; p < e2; p++) {
            int e = __ldg(g_eidx + p);
            int2 mm = __ldg(g_meta + p);
            float kv = g_K[mm.x * 64 + t];
            float fv = ef[(size_t)e * 64 + t];
            float4 va = *(const float4*)(g_V + mm.x * 64 + h8);
            float4 vb = *(const float4*)(g_V + mm.x * 64 + h8 + 4);
            float a = fmaxf(kv + fv, 0.0f) * __int_as_float(mm.y);
            acc[0] += a * va.x; acc[1] += a * va.y; acc[2] += a * va.z; acc[3] += a * va.w;
            acc[4] += a * vb.x; acc[5] += a * vb.y; acc[6] += a * vb.z; acc[7] += a * vb.w;
        }
    }

    g_MA4[(size_t)node * 64 + t] = pack8(acc);
    h_epilogue64(node, t, acc, __ldg(hopwise + 1), out);
}

// ---------------- prop hops + fused H-update (64 threads/node) ---------------
__global__ void __launch_bounds__(256) k_prop(const uint4* __restrict__ Msrc,
                                              uint4* __restrict__ Mdst, int writeM,
                                              int hop, const float* __restrict__ hopwise,
                                              float* __restrict__ out) {
    int node = g_order[blockIdx.x * 4 + (threadIdx.x >> 6)];
    int t = threadIdx.x & 63;

    float acc[8];
#pragma unroll
    for (int j = 0; j < 8; j++) acc[j] = 0.0f;

    int beg = g_ptr[node], end = g_ptr[node + 1];
    int p = beg;
    for (; p + 8 <= end; p += 8) {
        int2 mm[8];
        uint4 A[8];
#pragma unroll
        for (int q = 0; q < 8; q++) mm[q] = __ldg(g_meta + p + q);
#pragma unroll
        for (int q = 0; q < 8; q++) A[q] = Msrc[(size_t)mm[q].x * 64 + t];
#pragma unroll
        for (int q = 0; q < 8; q++) acc8(acc, A[q], __int_as_float(mm[q].y));
    }
    for (; p + 4 <= end; p += 4) {
        int2 mm[4];
        uint4 A[4];
#pragma unroll
        for (int q = 0; q < 4; q++) mm[q] = __ldg(g_meta + p + q);
#pragma unroll
        for (int q = 0; q < 4; q++) A[q] = Msrc[(size_t)mm[q].x * 64 + t];
#pragma unroll
        for (int q = 0; q < 4; q++) acc8(acc, A[q], __int_as_float(mm[q].y));
    }
    for (; p < end; p++) {
        int2 mm = __ldg(g_meta + p);
        uint4 A = Msrc[(size_t)mm.x * 64 + t];
        acc8(acc, A, __int_as_float(mm.y));
    }

    if (writeM) Mdst[(size_t)node * 64 + t] = pack8(acc);
    h_epilogue64(node, t, acc, __ldg(hopwise + hop), out);
}

// ---------------- launch -----------------------------------------------------
extern "C" void kernel_launch(void* const* d_in, const int* in_sizes, int n_in,
                              void* d_out, int out_size) {
    const float* x  = (const float*)d_in[0];
    const int*   ei = (const int*)d_in[1];
    const float* ef = (const float*)d_in[2];
    const float* ew = (const float*)d_in[3];
    const float* Wq = (const float*)d_in[4];
    const float* bq = (const float*)d_in[5];
    const float* Wk = (const float*)d_in[6];
    const float* bk = (const float*)d_in[7];
    const float* Wv = (const float*)d_in[8];
    const float* bv = (const float*)d_in[9];
    const float* hw = (const float*)d_in[10];
    const int* row = ei;
    const int* col = ei + EE;
    float* out = (float*)d_out;

    uint4 *dMA, *dMB;
    void* dcnt;
    cudaGetSymbolAddress((void**)&dMA, g_MA4);
    cudaGetSymbolAddress((void**)&dMB, g_MB4);
    cudaGetSymbolAddress(&dcnt, g_cnt);

    cudaMemsetAsync(dcnt, 0, NN * sizeof(int));
    k_count_qkv<<<1250, 256>>>(col, x, Wq, bq, Wk, bk, Wv, bv, hw, out);
    k_scan<<<1, 1024>>>();
    k_place<<<(EE + 255) / 256, 256>>>(col);

    k_hop0<<<2500, 256>>>(row, ew, ef, hw, out);         // sort+gather+hop0 -> MA
    k_prop<<<2500, 256>>>(dMA, dMB, 1, 2, hw, out);      // MA -> MB
    k_prop<<<2500, 256>>>(dMB, dMA, 0, 3, hw, out);      // MB read-only
}